// round 17
// baseline (speedup 1.0000x reference)
#include <cuda_runtime.h>
#include <cuda_fp16.h>
#include <cstdint>

// vaeVectorQuantizer: x[N=131072, D=64], E[D=64, K=1024]
// R16 = R14 structure (proven 125.4us) + cheap epilogue only:
//   hot key' = fmaf(-2, acc, esq+32)  (ys dropped: gaps are shift-invariant)
//   packed (keybits&~0x3FF)|code, top-2-min via 1 LOP3 + 3 IMNMX per key
//   rows with gap < EPS get exact fp32 coalesced rescan (reference rounding).
// MMA loop, B tiles, prep kernels identical to R14. occupancy 3.

#define D_DIM 64
#define K_DIM 1024
#define ROWS_PER_CTA 64
#define NTILE 128
#define NTILES 8
#define MTHREADS 256
#define EPS 2e-2f

#define PADROW 144
#define SM_X     0                         // 64 * 144 = 9216
#define SM_B     9216
#define B_BYTES  (NTILE * 64 * 2)          // 16384 per tile (fragment-packed h1)
#define SM_ESQ   (SM_B + 2 * B_BYTES)      // 41984 (true e_sq, rescan)
#define SM_E32   (SM_ESQ + 4096)           // 46080 (e_sq + 32, hot loop)
#define SM_YS    (SM_E32 + 4096)           // 50176 (64 floats)
#define SM_MRG   (SM_YS + 256)             // 50432: qv[4][64], qv2[4][64] (uint)
#define SM_CIDX  (SM_MRG + 2048)           // 52480
#define SM_XROW  (SM_CIDX + 256)           // 52736
#define SM_LIST  (SM_XROW + 256)           // 52992
#define SM_CNT   (SM_LIST + 256)           // 53248
#define SM_WRED  (SM_CNT + 16)             // 53264
#define SM_TOTAL 53376

__device__ float g_esq[K_DIM];
__device__ float g_ET[K_DIM * D_DIM];          // [k][d] fp32: gather table
__device__ uint2 g_Bf[NTILES * 4 * 16 * 32];   // [t][kc][nf][lane] h1 fragments

__device__ __forceinline__ uint32_t smem_u32(const void* p) {
    uint32_t a;
    asm("{ .reg .u64 t; cvta.to.shared.u64 t, %1; cvt.u32.u64 %0, t; }" : "=r"(a) : "l"(p));
    return a;
}
__device__ __forceinline__ void cp16(uint32_t dst, const void* src) {
    asm volatile("cp.async.cg.shared.global [%0], [%1], 16;" :: "r"(dst), "l"(src));
}
#define CP_COMMIT() asm volatile("cp.async.commit_group;" ::: "memory")
#define CP_WAIT(N)  asm volatile("cp.async.wait_group %0;" :: "n"(N) : "memory")

__device__ __forceinline__ void mma16816h(float* c, uint32_t a0, uint32_t a1,
                                          uint32_t a2, uint32_t a3,
                                          uint32_t b0, uint32_t b1) {
    asm volatile(
        "mma.sync.aligned.m16n8k16.row.col.f32.f16.f16.f32 "
        "{%0,%1,%2,%3}, {%4,%5,%6,%7}, {%8,%9}, {%0,%1,%2,%3};"
        : "+f"(c[0]), "+f"(c[1]), "+f"(c[2]), "+f"(c[3])
        : "r"(a0), "r"(a1), "r"(a2), "r"(a3), "r"(b0), "r"(b1));
}

// compensated accumulate of v*v (exact product + 2Sum) — no FP64 anywhere
__device__ __forceinline__ void csq(float v, float& s, float& comp) {
    float p = v * v;
    float e = fmaf(v, v, -p);
    float hi = s + p;
    float bb = hi - s;
    float err = (s - (hi - bb)) + (p - bb);
    s = hi;
    comp += err + e;
}
__device__ __forceinline__ void cmerge(float os, float ocmp, float& s, float& comp) {
    float hi = s + os;
    float bb = hi - s;
    float err = (s - (hi - bb)) + (os - bb);
    s = hi;
    comp += ocmp + err;
}

// pack positive fp32 key + 10-bit code (uint order == float order; tie->low code)
__device__ __forceinline__ uint32_t packk(float f, int code) {
    return (__float_as_uint(f) & 0xFFFFFC00u) | (uint32_t)code;
}
// top-2 MIN tracking: v2 = min(v2, max(v1,k)); v1 = min(v1,k)
__device__ __forceinline__ void trk(uint32_t kp, uint32_t& v1, uint32_t& v2) {
    uint32_t t = max(v1, kp);
    v2 = min(v2, t);
    v1 = min(v1, kp);
}

// ---------------- prep: coalesced e_sq + transposed gather table ----------------
__global__ void vq_prep(const float* __restrict__ E) {
    __shared__ float T[64][33];
    const int tid = threadIdx.x, lane = tid & 31, w = tid >> 5;
    const int k0 = blockIdx.x * 32;
#pragma unroll
    for (int dd = 0; dd < 8; ++dd) {
        int d = w * 8 + dd;
        T[d][lane] = E[d * K_DIM + k0 + lane];
    }
    __syncthreads();
    const int k = tid >> 3;
    const int dseg = (tid & 7) * 8;
    float s = 0.f, comp = 0.f;
#pragma unroll
    for (int j = 0; j < 8; ++j) csq(T[dseg + j][k], s, comp);
#pragma unroll
    for (int off = 1; off <= 4; off <<= 1) {
        float os   = __shfl_xor_sync(0xffffffffu, s, off);
        float ocmp = __shfl_xor_sync(0xffffffffu, comp, off);
        cmerge(os, ocmp, s, comp);
    }
    if ((tid & 7) == 0) g_esq[k0 + k] = s + comp;
    float4 a, b;
    a.x = T[dseg + 0][k]; a.y = T[dseg + 1][k]; a.z = T[dseg + 2][k]; a.w = T[dseg + 3][k];
    b.x = T[dseg + 4][k]; b.y = T[dseg + 5][k]; b.z = T[dseg + 6][k]; b.w = T[dseg + 7][k];
    *(float4*)(g_ET + (k0 + k) * D_DIM + dseg)     = a;
    *(float4*)(g_ET + (k0 + k) * D_DIM + dseg + 4) = b;
}

// ---------------- prep: B h1 fragments in mma lane order ----------------
__global__ void vq_prep_b(const float* __restrict__ E) {
    int idx = blockIdx.x * blockDim.x + threadIdx.x;   // 16384 total
    int lane = idx & 31;
    int x1 = idx >> 5;
    int nf = x1 & 15;
    int x2 = x1 >> 4;
    int kc = x2 & 3;
    int t = x2 >> 2;

    int code = t * 128 + nf * 8 + (lane >> 2);
    int c = lane & 3;
    uint32_t r[2];
#pragma unroll
    for (int m = 0; m < 2; ++m) {
        int d0 = kc * 16 + c * 2 + m * 8;
        __half2 pk = __halves2half2(__float2half_rn(E[d0 * K_DIM + code]),
                                    __float2half_rn(E[(d0 + 1) * K_DIM + code]));
        r[m] = *(uint32_t*)&pk;
    }
    g_Bf[idx] = make_uint2(r[0], r[1]);
}

// ---------------- main ----------------
__global__ __launch_bounds__(MTHREADS, 3)
void vq_tc(const float* __restrict__ x, const float* __restrict__ E,
           float* __restrict__ out) {
    extern __shared__ __align__(16) char smem[];
    const int tid = threadIdx.x;
    const int wid = tid >> 5;
    const int lane = tid & 31;
    const size_t rowbase = (size_t)blockIdx.x * ROWS_PER_CTA;

    float* esq_s = (float*)(smem + SM_ESQ);
    float* e32_s = (float*)(smem + SM_E32);
    float* ys_sh = (float*)(smem + SM_YS);
    int*   cidx  = (int*)(smem + SM_CIDX);
    const uint32_t sB_u32 = smem_u32(smem + SM_B);

    {
        float4 ev = *(const float4*)(g_esq + 4 * tid);
        *(float4*)(esq_s + 4 * tid) = ev;
        ev.x += 32.f; ev.y += 32.f; ev.z += 32.f; ev.w += 32.f;
        *(float4*)(e32_s + 4 * tid) = ev;
    }
    if (tid == 0) *(int*)(smem + SM_CNT) = 0;

    // ---- prefetch B tile 0
    {
        const char* src = (const char*)g_Bf;
#pragma unroll
        for (int i = 0; i < 4; ++i)
            cp16(sB_u32 + i * 4096 + tid * 16, src + i * 4096 + tid * 16);
        CP_COMMIT();
    }

    // ---- x: h1 fp16 into padded smem + compensated-fp32 row norms
    {
        int r = tid >> 2, dq = (tid & 3) * 16;
        const float* xr = x + (rowbase + r) * D_DIM + dq;
        char* xs = smem + SM_X + r * PADROW;
        float s = 0.f, comp = 0.f;
#pragma unroll
        for (int i = 0; i < 4; ++i) {
            float4 v = *(const float4*)(xr + 4 * i);
            int d0 = dq + 4 * i;
            csq(v.x, s, comp); csq(v.y, s, comp);
            csq(v.z, s, comp); csq(v.w, s, comp);
            *(__half2*)(xs + d0 * 2)     = __halves2half2(__float2half_rn(v.x), __float2half_rn(v.y));
            *(__half2*)(xs + d0 * 2 + 4) = __halves2half2(__float2half_rn(v.z), __float2half_rn(v.w));
        }
#pragma unroll
        for (int off = 1; off <= 2; off <<= 1) {
            float os   = __shfl_xor_sync(0xffffffffu, s, off);
            float ocmp = __shfl_xor_sync(0xffffffffu, comp, off);
            cmerge(os, ocmp, s, comp);
        }
        if ((tid & 3) == 0) ys_sh[r] = s + comp;
    }

    const int cq = wid >> 1;           // column quarter (32 codes)
    const int wg = wid & 1;            // row group (32 rows)
    const int g = lane >> 2, c = lane & 3;

    __syncthreads();

    const char* aRow[2][2];
#pragma unroll
    for (int mf = 0; mf < 2; ++mf)
#pragma unroll
        for (int h = 0; h < 2; ++h)
            aRow[mf][h] = smem + SM_X + (wg * 32 + mf * 16 + h * 8 + g) * PADROW + c * 4;

    uint32_t v1p[2][2] = {{0xFFFFFFFFu, 0xFFFFFFFFu}, {0xFFFFFFFFu, 0xFFFFFFFFu}};
    uint32_t v2p[2][2] = {{0xFFFFFFFFu, 0xFFFFFFFFu}, {0xFFFFFFFFu, 0xFFFFFFFFu}};

    for (int t = 0; t < NTILES; ++t) {
        const int buf = t & 1;
        if (t + 1 < NTILES) {
            const char* src = (const char*)g_Bf + (t + 1) * B_BYTES;
            uint32_t dst = sB_u32 + (buf ^ 1) * B_BYTES;
#pragma unroll
            for (int i = 0; i < 4; ++i)
                cp16(dst + i * 4096 + tid * 16, src + i * 4096 + tid * 16);
            CP_COMMIT();
            CP_WAIT(1);
        } else {
            CP_WAIT(0);
        }
        __syncthreads();

        float acc[4][2][4];
#pragma unroll
        for (int nf = 0; nf < 4; ++nf)
#pragma unroll
            for (int mf = 0; mf < 2; ++mf)
#pragma unroll
                for (int j = 0; j < 4; ++j) acc[nf][mf][j] = 0.f;

#pragma unroll
        for (int kc = 0; kc < 4; ++kc) {
            uint32_t A[2][4];
#pragma unroll
            for (int mf = 0; mf < 2; ++mf) {
                const char* a0p = aRow[mf][0] + kc * 32;
                const char* a1p = aRow[mf][1] + kc * 32;
                A[mf][0] = *(const uint32_t*)(a0p);
                A[mf][1] = *(const uint32_t*)(a1p);
                A[mf][2] = *(const uint32_t*)(a0p + 16);
                A[mf][3] = *(const uint32_t*)(a1p + 16);
            }
            const uint2* bp = (const uint2*)(smem + SM_B + buf * B_BYTES + kc * 4096)
                              + cq * 128 + lane;
            uint2 B[4];
#pragma unroll
            for (int nf = 0; nf < 4; ++nf) B[nf] = bp[nf * 32];
#pragma unroll
            for (int mf = 0; mf < 2; ++mf)
#pragma unroll
                for (int nf = 0; nf < 4; ++nf)
                    mma16816h(acc[nf][mf], A[mf][0], A[mf][1], A[mf][2], A[mf][3],
                              B[nf].x, B[nf].y);
        }

        // ---- epilogue: key' = fmaf(-2, acc, esq+32); packed top-2-min
#pragma unroll
        for (int nf = 0; nf < 4; ++nf) {
            int cb = t * NTILE + cq * 32 + nf * 8 + 2 * c;
            float e0 = e32_s[cb], e1 = e32_s[cb + 1];
#pragma unroll
            for (int mf = 0; mf < 2; ++mf) {
                float k00 = fmaf(-2.f, acc[nf][mf][0], e0);
                float k01 = fmaf(-2.f, acc[nf][mf][1], e1);
                float k10 = fmaf(-2.f, acc[nf][mf][2], e0);
                float k11 = fmaf(-2.f, acc[nf][mf][3], e1);
                trk(packk(k00, cb),     v1p[mf][0], v2p[mf][0]);
                trk(packk(k01, cb + 1), v1p[mf][0], v2p[mf][0]);
                trk(packk(k10, cb),     v1p[mf][1], v2p[mf][1]);
                trk(packk(k11, cb + 1), v1p[mf][1], v2p[mf][1]);
            }
        }
        __syncthreads();
    }

    // ---- merge across the 4 lanes (c) sharing each row
#pragma unroll
    for (int off = 1; off <= 2; off <<= 1) {
#pragma unroll
        for (int mf = 0; mf < 2; ++mf)
#pragma unroll
            for (int h = 0; h < 2; ++h) {
                uint32_t o1 = __shfl_xor_sync(0xffffffffu, v1p[mf][h], off);
                uint32_t o2 = __shfl_xor_sync(0xffffffffu, v2p[mf][h], off);
                uint32_t tt = max(v1p[mf][h], o1);
                v2p[mf][h] = min(min(v2p[mf][h], o2), tt);
                v1p[mf][h] = min(v1p[mf][h], o1);
            }
    }
    // ---- publish per-quarter packed top-2, merge across quarters
    uint32_t* qv  = (uint32_t*)(smem + SM_MRG);      // [cq][row]
    uint32_t* qv2 = (uint32_t*)(smem + SM_MRG + 1024);
    if (c == 0) {
#pragma unroll
        for (int mf = 0; mf < 2; ++mf)
#pragma unroll
            for (int h = 0; h < 2; ++h) {
                int r = cq * 64 + wg * 32 + mf * 16 + h * 8 + g;
                qv[r] = v1p[mf][h]; qv2[r] = v2p[mf][h];
            }
    }
    __syncthreads();
    int* list = (int*)(smem + SM_LIST);
    int* cnt  = (int*)(smem + SM_CNT);
    if (tid < ROWS_PER_CTA) {
        uint32_t V1 = qv[tid], V2 = qv2[tid];
#pragma unroll
        for (int q = 1; q < 4; ++q) {
            uint32_t o1 = qv[q * 64 + tid], o2 = qv2[q * 64 + tid];
            uint32_t tt = max(V1, o1);
            V2 = min(min(V2, o2), tt);
            V1 = min(V1, o1);
        }
        cidx[tid] = (int)(V1 & 1023u);
        float g1 = __uint_as_float(V1 & 0xFFFFFC00u);
        float g2 = __uint_as_float(V2 & 0xFFFFFC00u);
        if (g2 - g1 < EPS) {           // ambiguous -> exact rescan
            int slot = atomicAdd(cnt, 1);
            list[slot] = tid;
        }
    }
    __syncthreads();

    // ---- exact fp32 rescan of flagged rows (reference rounding, tie->lowest)
    const int nflag = *cnt;
    float* xrow = (float*)(smem + SM_XROW);
    float* wrv  = (float*)(smem + SM_WRED);
    int*   wrc  = (int*)(smem + SM_WRED + 32);
    for (int i = 0; i < nflag; ++i) {
        int r = list[i];
        if (tid < 16)
            ((float4*)xrow)[tid] = ((const float4*)(x + (rowbase + r) * D_DIM))[tid];
        __syncthreads();
        float ys = ys_sh[r];
        float dot[4] = {0.f, 0.f, 0.f, 0.f};
#pragma unroll
        for (int d = 0; d < D_DIM; ++d) {
            float xv = xrow[d];
            const float* Ed = E + d * K_DIM + tid;
#pragma unroll
            for (int kk = 0; kk < 4; ++kk)
                dot[kk] = fmaf(xv, Ed[kk * MTHREADS], dot[kk]);
        }
        float bestv = 3.402823466e38f;
        int   bestc = 0;
#pragma unroll
        for (int kk = 0; kk < 4; ++kk) {
            int k = tid + kk * MTHREADS;
            float key = fmaf(-2.f, dot[kk], __fadd_rn(ys, esq_s[k]));
            if (key < bestv || (key == bestv && k < bestc)) { bestv = key; bestc = k; }
        }
#pragma unroll
        for (int off = 16; off >= 1; off >>= 1) {
            float ov = __shfl_xor_sync(0xffffffffu, bestv, off);
            int   oc = __shfl_xor_sync(0xffffffffu, bestc, off);
            if (ov < bestv || (ov == bestv && oc < bestc)) { bestv = ov; bestc = oc; }
        }
        if (lane == 0) { wrv[wid] = bestv; wrc[wid] = bestc; }
        __syncthreads();
        if (tid == 0) {
            float bv = wrv[0]; int bcn = wrc[0];
#pragma unroll
            for (int w = 1; w < 8; ++w) {
                float v = wrv[w]; int cc = wrc[w];
                if (v < bv || (v == bv && cc < bcn)) { bv = v; bcn = cc; }
            }
            cidx[r] = bcn;
        }
        __syncthreads();
    }

    // ---- gather output rows from transposed codebook
    float* og = out + rowbase * D_DIM;
#pragma unroll
    for (int it = 0; it < 4; ++it) {
        int i  = tid + it * MTHREADS;
        int r  = i >> 4;
        int d0 = (i & 15) << 2;
        *(float4*)(og + r * D_DIM + d0) = *(const float4*)(g_ET + cidx[r] * D_DIM + d0);
    }
}

extern "C" void kernel_launch(void* const* d_in, const int* in_sizes, int n_in,
                              void* d_out, int out_size) {
    const float* x = (const float*)d_in[0];
    const float* E = (const float*)d_in[1];
    float* out = (float*)d_out;
    int N = in_sizes[0] / D_DIM;  // 131072

    cudaFuncSetAttribute(vq_tc, cudaFuncAttributeMaxDynamicSharedMemorySize, SM_TOTAL);
    vq_prep<<<K_DIM / 32, MTHREADS>>>(E);
    vq_prep_b<<<(NTILES * 4 * 16 * 32) / MTHREADS, MTHREADS>>>(E);
    vq_tc<<<N / ROWS_PER_CTA, MTHREADS, SM_TOTAL>>>(x, E, out);
}